// round 9
// baseline (speedup 1.0000x reference)
#include <cuda_runtime.h>
#include <cuda_fp16.h>

#define NTHREADS 512
#define GRIDX 304          // 2 CTAs x 152 SMs, persistent
#define UH 80              // halves per u row
#define XSTR 68            // floats per x row
#define PFS 80             // halves per facet block in partial buffer
#define PWS 648            // halves per warp block

// smem bytes: stage 81920 | us 1280 | xs 2176 | part 20736
#define SMEM_BYTES 106112

// Reduce-scatter 8 values over lane bits 1-3: lane (b1,b2,b3) ends with the
// 8-lane-group sum of v[b1 + 2*b2 + 4*b3].
__device__ __forceinline__ float reduce_scatter8(const float* v, int lane) {
    float a[4];
    {
        const bool hb = (lane & 8) != 0;
        #pragma unroll
        for (int k = 0; k < 4; k++) {
            float snd = hb ? v[k] : v[k + 4];
            float rcv = __shfl_xor_sync(0xffffffffu, snd, 8);
            a[k] = (hb ? v[k + 4] : v[k]) + rcv;
        }
    }
    float c[2];
    {
        const bool hb = (lane & 4) != 0;
        #pragma unroll
        for (int k = 0; k < 2; k++) {
            float snd = hb ? a[k] : a[k + 2];
            float rcv = __shfl_xor_sync(0xffffffffu, snd, 4);
            c[k] = (hb ? a[k + 2] : a[k]) + rcv;
        }
    }
    {
        const bool hb = (lane & 2) != 0;
        float snd = hb ? c[0] : c[1];
        float rcv = __shfl_xor_sync(0xffffffffu, snd, 2);
        return (hb ? c[1] : c[0]) + rcv;
    }
}

// Prefetch loads [S, S+N) of next batch's z into the stage buffer (fp16).
template<int S, int N>
__device__ __forceinline__ void pf(const float4* gzn, __half* swr, bool hn) {
    if (!hn) return;
    float4 v[N];
    #pragma unroll
    for (int j = 0; j < N; j++) v[j] = __ldcs(gzn + (S + j) * 32);
    #pragma unroll
    for (int j = 0; j < N; j++) {
        constexpr int dummy = 0; (void)dummy;
        int i = S + j;
        __half2 h0 = __floats2half2_rn(v[j].x, v[j].y);
        __half2 h1 = __floats2half2_rn(v[j].z, v[j].w);
        uint2 st;
        st.x = *(unsigned*)&h0;
        st.y = *(unsigned*)&h1;
        *(uint2*)(swr + 640 * (i >> 2) + 160 * (i & 3)) = st;
    }
}

__global__ __launch_bounds__(NTHREADS, 2)
void hete_attention_kernel(const float* __restrict__ feat,
                           const float* __restrict__ meta,
                           float* __restrict__ out,
                           int Btot)
{
    extern __shared__ char smemc[];
    __half* stage = (__half*)smemc;                 // [64 n][8 f][80 h]
    __half* us    = (__half*)(smemc + 81920);       // [8][80] halves
    float*  xs    = (float*)(smemc + 83200);        // [8][68]
    __half* part  = (__half*)(smemc + 85376);       // [16 w][8 f][80]

    const int t    = threadIdx.x;
    const int lane = t & 31;
    const int w    = t >> 5;
    const int hi   = lane >> 4;
    const int po   = lane & 1;
    const int a    = (lane >> 1) & 7;
    const int dq   = lane & 15;

    // compute-ownership (identical to verified round-8 mapping):
    // thread rows k=0..7: n = 4w + (k>>1), f = 4*(k&1) + 2*po + hi, d = 8a..8a+7
    const int fA = 2 * po + hi;
    const int fB = fA + 4;
    const __half* uA = us + fA * UH + a * 8;
    const __half* uB = us + fB * UH + a * 8;
    __half* pA = part + w * PWS + fA * PFS + a * 8;
    __half* pB = part + w * PWS + fB * PFS + a * 8;
    const int gidx = lane & 17;

    // stage pointers: write (coalesced-load layout), read (ownership layout)
    __half* swr = stage + 2560 * w + 80 * hi + 4 * dq;
    const __half* srd = stage + 2560 * w + 160 * po + 80 * hi + 8 * a;

    int bi = blockIdx.x;
    float2 xv = make_float2(0.f, 0.f);

    // ---- prologue: stage z(bi), preload x(bi) ----
    if (bi < Btot) {
        const float4* gz0 = (const float4*)(meta + (size_t)bi * 32768) + w * 512 + lane;
        pf<0, 4>(gz0, swr, true);
        pf<4, 4>(gz0, swr, true);
        pf<8, 4>(gz0, swr, true);
        pf<12, 4>(gz0, swr, true);
        if (w < 8) xv = *(const float2*)(feat + (size_t)bi * 512 + w * 64 + lane * 2);
    }
    __syncthreads();

    for (; bi < Btot; bi += GRIDX) {
        const int  bn = bi + GRIDX;
        const bool hn = bn < Btot;
        const float4* gzn = (const float4*)(meta + (size_t)bn * 32768) + w * 512 + lane;

        // ---- x norm from preloaded regs (warps 0..7) ----
        if (w < 8) {
            float s = xv.x * xv.x + xv.y * xv.y;
            #pragma unroll
            for (int o = 16; o; o >>= 1) s += __shfl_xor_sync(0xffffffffu, s, o);
            float r = rsqrtf(fmaxf(s, 1e-24f));
            float2 nv = make_float2(xv.x * r, xv.y * r);
            *(float2*)(xs + w * XSTR + lane * 2) = nv;
            *(__half2*)(us + w * UH + lane * 2) = __floats2half2_rn(nv.x, nv.y);
        }

        // ---- read stage -> zr (already in ownership layout) ----
        __half2 zr[32];
        #pragma unroll
        for (int k = 0; k < 8; k++)
            *(uint4*)&zr[4 * k] = *(const uint4*)(srd + 640 * (k >> 1) + 320 * (k & 1));

        // ---- row reciprocal norms ----
        float rzv;
        {
            float sd[8];
            #pragma unroll
            for (int k = 0; k < 8; k++) {
                __half2 h = __hmul2(zr[4 * k], zr[4 * k]);
                h = __hfma2(zr[4 * k + 1], zr[4 * k + 1], h);
                h = __hfma2(zr[4 * k + 2], zr[4 * k + 2], h);
                h = __hfma2(zr[4 * k + 3], zr[4 * k + 3], h);
                float2 fx = __half22float2(h);
                sd[k] = fx.x + fx.y;
            }
            float S = reduce_scatter8(sd, lane);
            rzv = rsqrtf(fmaxf(S, 1e-24f));
        }
        __syncthreads();                            // stage drained; us/xs ready

        #pragma unroll
        for (int it = 0; it < 3; it++) {
            // prefetch chunk before dots (slots 0,2,4 -> loads 0-2, 6-8, 12-13)
            if (it == 0) pf<0, 3>(gzn, swr, hn);
            else if (it == 1) pf<6, 3>(gzn, swr, hn);
            else pf<12, 2>(gzn, swr, hn);

            // ---- u chunks for the 2 facets ----
            __half2 uhA[4], uhB[4];
            *(uint4*)uhA = *(const uint4*)uA;
            *(uint4*)uhB = *(const uint4*)uB;

            // ---- 8 row-dots over own 8 d ----
            float dj[8];
            #pragma unroll
            for (int k = 0; k < 8; k++) {
                const __half2* uu = (k & 1) ? uhB : uhA;
                __half2 h = __hmul2(zr[4 * k], uu[0]);
                h = __hfma2(zr[4 * k + 1], uu[1], h);
                h = __hfma2(zr[4 * k + 2], uu[2], h);
                h = __hfma2(zr[4 * k + 3], uu[3], h);
                float2 fx = __half22float2(h);
                dj[k] = fx.x + fx.y;
            }

            // ---- scatter-reduce -> logit; softmax over f ----
            float L = reduce_scatter8(dj, lane) * rzv;
            float e = __expf(L);                    // cosines in [-1,1]
            float s = e;
            s += __shfl_xor_sync(0xffffffffu, s, 1);
            s += __shfl_xor_sync(0xffffffffu, s, 2);
            s += __shfl_xor_sync(0xffffffffu, s, 16);
            float p_eff = __fdividef(e, s) * rzv;

            // ---- packed fp16 gather of own 8 rows' p ----
            __half ph = __float2half(p_eff);
            unsigned pv = (unsigned)__half_as_ushort(ph);
            unsigned p8 = __shfl_xor_sync(0xffffffffu, pv, 8);
            __half2 P2 = __halves2half2(ph, __ushort_as_half((unsigned short)p8));
            unsigned P2u = *(unsigned*)&P2;
            __half2 g[4];
            #pragma unroll
            for (int k = 0; k < 4; k++) {
                unsigned gu = __shfl_sync(0xffffffffu, P2u, gidx | (k << 1));
                g[k] = *(__half2*)&gu;
            }

            // ---- pass 2 (fp16 accumulate) ----
            __half2 accA[4], accB[4];
            {
                __half2 ph0 = __low2half2(g[0]);
                __half2 ph1 = __low2half2(g[1]);
                #pragma unroll
                for (int r = 0; r < 4; r++) {
                    accA[r] = __hmul2(zr[r], ph0);
                    accB[r] = __hmul2(zr[4 + r], ph1);
                }
                #pragma unroll
                for (int k = 2; k < 8; k++) {
                    __half2 pk = (k < 4) ? __low2half2(g[k]) : __high2half2(g[k - 4]);
                    __half2* acc = (k & 1) ? accB : accA;
                    #pragma unroll
                    for (int r = 0; r < 4; r++)
                        acc[r] = __hfma2(zr[4 * k + r], pk, acc[r]);
                }
            }
            *(uint4*)pA = *(uint4*)accA;
            *(uint4*)pB = *(uint4*)accB;
            __syncthreads();                        // partials visible

            // prefetch chunk between barriers (slots 1,3,5)
            if (it == 0) pf<3, 3>(gzn, swr, hn);
            else if (it == 1) pf<9, 3>(gzn, swr, hn);
            else pf<14, 2>(gzn, swr, hn);

            // ---- epilogue: warp f<8 combines 16 partials (fp32), +x ----
            if (w < 8) {
                int d0 = lane * 2;
                float2 v = *(const float2*)(xs + w * XSTR + d0);
                #pragma unroll
                for (int gg = 0; gg < 16; gg++) {
                    __half2 hv = *(const __half2*)(part + gg * PWS + w * PFS + d0);
                    float2 fv = __half22float2(hv);
                    v.x += fv.x; v.y += fv.y;
                }
                if (it < 2) {
                    float s2 = v.x * v.x + v.y * v.y;
                    #pragma unroll
                    for (int o = 16; o; o >>= 1) s2 += __shfl_xor_sync(0xffffffffu, s2, o);
                    float r = rsqrtf(fmaxf(s2, 1e-24f));
                    *(__half2*)(us + w * UH + d0) = __floats2half2_rn(v.x * r, v.y * r);
                } else {
                    *(float2*)(out + (size_t)bi * 512 + w * 64 + d0) = v;
                }
            }
            // preload next batch's x during iter 0 (after xv's last use)
            if (it == 0 && w < 8 && hn)
                xv = *(const float2*)(feat + (size_t)bn * 512 + w * 64 + lane * 2);

            __syncthreads();                        // u ready / end-of-batch fence
        }
    }
}

extern "C" void kernel_launch(void* const* d_in, const int* in_sizes, int n_in,
                              void* d_out, int out_size)
{
    const float* feat = (const float*)d_in[0];   // [B, 512]
    const float* meta = (const float*)d_in[1];   // [B, 64, 512]
    float* out = (float*)d_out;

    const int B = in_sizes[0] / 512;             // 2048

    cudaFuncSetAttribute(hete_attention_kernel,
                         cudaFuncAttributeMaxDynamicSharedMemorySize,
                         SMEM_BYTES);

    hete_attention_kernel<<<GRIDX, NTHREADS, SMEM_BYTES>>>(feat, meta, out, B);
}

// round 10
// speedup vs baseline: 1.1296x; 1.1296x over previous
#include <cuda_runtime.h>
#include <cuda_fp16.h>

#define NTHREADS 512
#define GRIDX 304          // 2 CTAs x 152 SMs, persistent
#define UH 80              // halves per u row
#define XSTR 68            // floats per x row
#define PFS 80             // halves per facet block in partial buffer
#define PWS 648            // halves per warp block
#define SRS 68             // stage row stride (floats); 68 mod 32 = 4 -> conflict-free
#define SWS 1360           // stage floats per warp (20 rows x 68)

// smem bytes: stage 87040 | us 1280 | xs 2176 | part 20736
#define SMEM_BYTES 111232

// Reduce-scatter 8 values over lane bits 1-3.
__device__ __forceinline__ float reduce_scatter8(const float* v, int lane) {
    float a[4];
    {
        const bool hb = (lane & 8) != 0;
        #pragma unroll
        for (int k = 0; k < 4; k++) {
            float snd = hb ? v[k] : v[k + 4];
            float rcv = __shfl_xor_sync(0xffffffffu, snd, 8);
            a[k] = (hb ? v[k + 4] : v[k]) + rcv;
        }
    }
    float c[2];
    {
        const bool hb = (lane & 4) != 0;
        #pragma unroll
        for (int k = 0; k < 2; k++) {
            float snd = hb ? a[k] : a[k + 2];
            float rcv = __shfl_xor_sync(0xffffffffu, snd, 4);
            c[k] = (hb ? a[k + 2] : a[k]) + rcv;
        }
    }
    {
        const bool hb = (lane & 2) != 0;
        float snd = hb ? c[0] : c[1];
        float rcv = __shfl_xor_sync(0xffffffffu, snd, 2);
        return (hb ? c[1] : c[0]) + rcv;
    }
}

__global__ __launch_bounds__(NTHREADS, 2)
void hete_attention_kernel(const float* __restrict__ feat,
                           const float* __restrict__ meta,
                           float* __restrict__ out,
                           int Btot)
{
    extern __shared__ char smemc[];
    float*  stage = (float*)smemc;                  // [16 w][20 rows][68]
    __half* us    = (__half*)(smemc + 87040);       // [8][80] halves
    float*  xs    = (float*)(smemc + 88320);        // [8][68]
    __half* part  = (__half*)(smemc + 90496);       // [16 w][8 f][80]

    const int t    = threadIdx.x;
    const int lane = t & 31;
    const int w    = t >> 5;
    const int hi   = lane >> 4;
    const int po   = lane & 1;
    const int a    = (lane >> 1) & 7;
    const int dq   = lane & 15;

    // compute ownership (round-8 verified): rows k=0..7:
    // n = 4w + (k>>1), f = 4*(k&1) + 2*po + hi, d = 8a..8a+7
    const int fA = 2 * po + hi;
    const int fB = fA + 4;
    const __half* uA = us + fA * UH + a * 8;
    const __half* uB = us + fB * UH + a * 8;
    __half* pA = part + w * PWS + fA * PFS + a * 8;
    __half* pB = part + w * PWS + fB * PFS + a * 8;
    const int gidx = lane & 17;

    // stage addresses
    float* stageW = stage + w * SWS;
    const unsigned sdst0 = (unsigned)__cvta_generic_to_shared(stageW)
                         + (unsigned)((10 * hi) * SRS + 4 * dq) * 4u;   // cp.async dst base
    const float* rdp = stageW + (po + 10 * hi) * SRS + 8 * a;           // read base (k-stride 2*SRS)

    int bi = blockIdx.x;
    float2 xv = make_float2(0.f, 0.f);

    // ---- prologue: async-stage rows 0..9 of batch bi, preload x ----
    if (bi < Btot) {
        const float4* gsrc = (const float4*)(meta + (size_t)bi * 32768) + w * 512 + lane;
        #pragma unroll
        for (int i = 0; i < 10; i++)
            asm volatile("cp.async.cg.shared.global [%0], [%1], 16;\n"
                         :: "r"(sdst0 + (unsigned)(i * SRS * 4)), "l"(gsrc + i * 32));
        asm volatile("cp.async.commit_group;\n" ::: "memory");
        if (w < 8) xv = *(const float2*)(feat + (size_t)bi * 512 + w * 64 + lane * 2);
    }

    for (; bi < Btot; bi += GRIDX) {
        const int  bn = bi + GRIDX;
        const bool hn = bn < Btot;

        // ---- direct rows 10..15 of current batch (issue first, consume later) ----
        float4 dv[6];
        {
            const float4* gzc = (const float4*)(meta + (size_t)bi * 32768) + w * 512 + lane;
            #pragma unroll
            for (int j = 0; j < 6; j++) dv[j] = __ldcs(gzc + (10 + j) * 32);
        }

        // ---- x norm from preloaded regs (warps 0..7) ----
        if (w < 8) {
            float s = xv.x * xv.x + xv.y * xv.y;
            #pragma unroll
            for (int o = 16; o; o >>= 1) s += __shfl_xor_sync(0xffffffffu, s, o);
            float r = rsqrtf(fmaxf(s, 1e-24f));
            float2 nv = make_float2(xv.x * r, xv.y * r);
            *(float2*)(xs + w * XSTR + lane * 2) = nv;
            *(__half2*)(us + w * UH + lane * 2) = __floats2half2_rn(nv.x, nv.y);
        }

        // ---- staged rows ready; make all writes visible ----
        asm volatile("cp.async.wait_all;\n" ::: "memory");
        __syncthreads();

        // ---- stage -> zr rows k=0..4 (fp32 -> fp16) ----
        __half2 zr[32];
        #pragma unroll
        for (int k = 0; k < 5; k++) {
            float4 lo  = *(const float4*)(rdp + k * (2 * SRS));
            float4 hi4 = *(const float4*)(rdp + k * (2 * SRS) + 4);
            zr[4 * k]     = __floats2half2_rn(lo.x, lo.y);
            zr[4 * k + 1] = __floats2half2_rn(lo.z, lo.w);
            zr[4 * k + 2] = __floats2half2_rn(hi4.x, hi4.y);
            zr[4 * k + 3] = __floats2half2_rn(hi4.z, hi4.w);
        }

        // ---- direct rows -> zr[20..31]; transpose steps k=5..7 ----
        #pragma unroll
        for (int j = 0; j < 6; j++) {
            zr[20 + 2 * j]     = __floats2half2_rn(dv[j].x, dv[j].y);
            zr[20 + 2 * j + 1] = __floats2half2_rn(dv[j].z, dv[j].w);
        }
        #pragma unroll
        for (int k = 5; k < 8; k++) {
            unsigned a0 = *(unsigned*)&zr[4 * k];
            unsigned a1 = *(unsigned*)&zr[4 * k + 1];
            unsigned b0 = *(unsigned*)&zr[4 * k + 2];
            unsigned b1 = *(unsigned*)&zr[4 * k + 3];
            unsigned s0 = po ? a0 : b0;
            unsigned s1 = po ? a1 : b1;
            unsigned r0 = __shfl_xor_sync(0xffffffffu, s0, 1);
            unsigned r1 = __shfl_xor_sync(0xffffffffu, s1, 1);
            unsigned o0 = po ? r0 : a0, o1 = po ? r1 : a1;
            unsigned o2 = po ? b0 : r0, o3 = po ? b1 : r1;
            zr[4 * k]     = *(__half2*)&o0;
            zr[4 * k + 1] = *(__half2*)&o1;
            zr[4 * k + 2] = *(__half2*)&o2;
            zr[4 * k + 3] = *(__half2*)&o3;
        }

        // ---- row reciprocal norms ----
        float rzv;
        {
            float sd[8];
            #pragma unroll
            for (int k = 0; k < 8; k++) {
                __half2 h = __hmul2(zr[4 * k], zr[4 * k]);
                h = __hfma2(zr[4 * k + 1], zr[4 * k + 1], h);
                h = __hfma2(zr[4 * k + 2], zr[4 * k + 2], h);
                h = __hfma2(zr[4 * k + 3], zr[4 * k + 3], h);
                float2 fx = __half22float2(h);
                sd[k] = fx.x + fx.y;
            }
            float S = reduce_scatter8(sd, lane);
            rzv = rsqrtf(fmaxf(S, 1e-24f));
        }
        __syncthreads();                            // all stage reads complete

        // ---- launch async staging for NEXT batch; preload next x ----
        if (hn) {
            const float4* gsrc = (const float4*)(meta + (size_t)bn * 32768) + w * 512 + lane;
            #pragma unroll
            for (int i = 0; i < 10; i++)
                asm volatile("cp.async.cg.shared.global [%0], [%1], 16;\n"
                             :: "r"(sdst0 + (unsigned)(i * SRS * 4)), "l"(gsrc + i * 32));
            asm volatile("cp.async.commit_group;\n" ::: "memory");
            if (w < 8) xv = *(const float2*)(feat + (size_t)bn * 512 + w * 64 + lane * 2);
        }

        #pragma unroll
        for (int it = 0; it < 3; it++) {
            // ---- u chunks for the 2 facets ----
            __half2 uhA[4], uhB[4];
            *(uint4*)uhA = *(const uint4*)uA;
            *(uint4*)uhB = *(const uint4*)uB;

            // ---- 8 row-dots over own 8 d ----
            float dj[8];
            #pragma unroll
            for (int k = 0; k < 8; k++) {
                const __half2* uu = (k & 1) ? uhB : uhA;
                __half2 h = __hmul2(zr[4 * k], uu[0]);
                h = __hfma2(zr[4 * k + 1], uu[1], h);
                h = __hfma2(zr[4 * k + 2], uu[2], h);
                h = __hfma2(zr[4 * k + 3], uu[3], h);
                float2 fx = __half22float2(h);
                dj[k] = fx.x + fx.y;
            }

            // ---- scatter-reduce -> logit; softmax over f ----
            float L = reduce_scatter8(dj, lane) * rzv;
            float e = __expf(L);                    // cosines in [-1,1]
            float s = e;
            s += __shfl_xor_sync(0xffffffffu, s, 1);
            s += __shfl_xor_sync(0xffffffffu, s, 2);
            s += __shfl_xor_sync(0xffffffffu, s, 16);
            float p_eff = __fdividef(e, s) * rzv;

            // ---- packed fp16 gather of own 8 rows' p ----
            __half ph = __float2half(p_eff);
            unsigned pv = (unsigned)__half_as_ushort(ph);
            unsigned p8 = __shfl_xor_sync(0xffffffffu, pv, 8);
            __half2 P2 = __halves2half2(ph, __ushort_as_half((unsigned short)p8));
            unsigned P2u = *(unsigned*)&P2;
            __half2 g[4];
            #pragma unroll
            for (int k = 0; k < 4; k++) {
                unsigned gu = __shfl_sync(0xffffffffu, P2u, gidx | (k << 1));
                g[k] = *(__half2*)&gu;
            }

            // ---- pass 2 (fp16 accumulate) ----
            __half2 accA[4], accB[4];
            {
                __half2 ph0 = __low2half2(g[0]);
                __half2 ph1 = __low2half2(g[1]);
                #pragma unroll
                for (int r = 0; r < 4; r++) {
                    accA[r] = __hmul2(zr[r], ph0);
                    accB[r] = __hmul2(zr[4 + r], ph1);
                }
                #pragma unroll
                for (int k = 2; k < 8; k++) {
                    __half2 pk = (k < 4) ? __low2half2(g[k]) : __high2half2(g[k - 4]);
                    __half2* acc = (k & 1) ? accB : accA;
                    #pragma unroll
                    for (int r = 0; r < 4; r++)
                        acc[r] = __hfma2(zr[4 * k + r], pk, acc[r]);
                }
            }
            *(uint4*)pA = *(uint4*)accA;
            *(uint4*)pB = *(uint4*)accB;
            __syncthreads();                        // partials visible

            // ---- epilogue: warp f<8 combines 16 partials (fp32), +x ----
            if (w < 8) {
                int d0 = lane * 2;
                float2 v = *(const float2*)(xs + w * XSTR + d0);
                #pragma unroll
                for (int gg = 0; gg < 16; gg++) {
                    __half2 hv = *(const __half2*)(part + gg * PWS + w * PFS + d0);
                    float2 fv = __half22float2(hv);
                    v.x += fv.x; v.y += fv.y;
                }
                if (it < 2) {
                    float s2 = v.x * v.x + v.y * v.y;
                    #pragma unroll
                    for (int o = 16; o; o >>= 1) s2 += __shfl_xor_sync(0xffffffffu, s2, o);
                    float r = rsqrtf(fmaxf(s2, 1e-24f));
                    *(__half2*)(us + w * UH + d0) = __floats2half2_rn(v.x * r, v.y * r);
                } else {
                    *(float2*)(out + (size_t)bi * 512 + w * 64 + d0) = v;
                }
            }
            if (it < 2) __syncthreads();            // u ready for next iter
        }
    }
}

extern "C" void kernel_launch(void* const* d_in, const int* in_sizes, int n_in,
                              void* d_out, int out_size)
{
    const float* feat = (const float*)d_in[0];   // [B, 512]
    const float* meta = (const float*)d_in[1];   // [B, 64, 512]
    float* out = (float*)d_out;

    const int B = in_sizes[0] / 512;             // 2048

    cudaFuncSetAttribute(hete_attention_kernel,
                         cudaFuncAttributeMaxDynamicSharedMemorySize,
                         SMEM_BYTES);

    hete_attention_kernel<<<GRIDX, NTHREADS, SMEM_BYTES>>>(feat, meta, out, B);
}